// round 13
// baseline (speedup 1.0000x reference)
#include <cuda_runtime.h>
#include <cuda_fp16.h>
#include <math_constants.h>
#include <cstdint>

// Problem: z [32,256,32,32], embedding [1024,256]
constexpr int D    = 256;
constexpr int K    = 1024;
constexpr int HW   = 1024;
constexpr int NTOK = 32768;
constexpr int TM   = 128;        // tokens per CTA
constexpr int NB   = 32;         // codes per chunk
constexpr int NCHK = K / NB;     // 32

// smem offsets in u32 units
constexpr int S_AHI = 0;         // [128 tok][128 u32] 64KB
constexpr int S_ALO = 16384;
constexpr int S_B   = 32768;     // 2 bufs x (hi 4096 u32 + lo 4096 u32) = 64KB
constexpr int S_EH  = 49152;     // 1024 f32
constexpr int S_RI  = 50176;     // 128 i32
constexpr int S_RED = 50304;     // 256 f32
constexpr int SMEM_U32   = 50560;
constexpr int SMEM_BYTES = SMEM_U32 * 4;   // 202240

// ---- device scratch (static; zero-init, restored by consumers each replay) --
__device__ __align__(16) uint32_t g_Ahi[NTOK * 128];
__device__ __align__(16) uint32_t g_Alo[NTOK * 128];
__device__ __align__(16) uint32_t g_Bhi[K * 128];
__device__ __align__(16) uint32_t g_Blo[K * 128];
__device__ __align__(16) float g_dw[K * D];
__device__ float g_counts[K];
__device__ float g_loss;
__device__ float g_eh[K];                // 0.5*||e_k||^2

// ---------------- helpers ----------------
__device__ __forceinline__ uint32_t smaddr(const void* p) {
    uint32_t a;
    asm("{ .reg .u64 t; cvta.to.shared.u64 t, %1; cvt.u32.u64 %0, t; }"
        : "=r"(a) : "l"(p));
    return a;
}
__device__ __forceinline__ void cp16(uint32_t s, const void* g) {
    asm volatile("cp.async.cg.shared.global [%0], [%1], 16;" :: "r"(s), "l"(g));
}
__device__ __forceinline__ void ldsm4(uint32_t* r, uint32_t addr) {
    asm volatile("ldmatrix.sync.aligned.m8n8.x4.shared.b16 {%0,%1,%2,%3}, [%4];"
        : "=r"(r[0]), "=r"(r[1]), "=r"(r[2]), "=r"(r[3]) : "r"(addr));
}
// fp32-accumulate HMMA (main product)
__device__ __forceinline__ void mma_f16(float* c, const uint32_t* a,
                                        const uint32_t* b) {
    asm volatile("mma.sync.aligned.m16n8k16.row.col.f32.f16.f16.f32 "
        "{%0,%1,%2,%3},{%4,%5,%6,%7},{%8,%9},{%0,%1,%2,%3};"
        : "+f"(c[0]), "+f"(c[1]), "+f"(c[2]), "+f"(c[3])
        : "r"(a[0]), "r"(a[1]), "r"(a[2]), "r"(a[3]), "r"(b[0]), "r"(b[1]));
}
// fp16-accumulate HMMA (cross terms; c = 2x half2 regs covering same 4 elems)
__device__ __forceinline__ void mma_f16h(uint32_t* c, const uint32_t* a,
                                         const uint32_t* b) {
    asm volatile("mma.sync.aligned.m16n8k16.row.col.f16.f16.f16.f16 "
        "{%0,%1},{%2,%3,%4,%5},{%6,%7},{%0,%1};"
        : "+r"(c[0]), "+r"(c[1])
        : "r"(a[0]), "r"(a[1]), "r"(a[2]), "r"(a[3]), "r"(b[0]), "r"(b[1]));
}
__device__ __forceinline__ uint32_t packsplit(float v0, float v1, uint32_t& lo) {
    __half h0 = __float2half_rn(v0), h1 = __float2half_rn(v1);
    __half l0 = __float2half_rn(v0 - __half2float(h0));
    __half l1 = __float2half_rn(v1 - __half2float(h1));
    __half2 H = __halves2half2(h0, h1), L = __halves2half2(l0, l1);
    lo = *reinterpret_cast<uint32_t*>(&L);
    return *reinterpret_cast<uint32_t*>(&H);
}

// ---------------- split z -> fp16 hi/lo, token-major (half grid per call) ----
__global__ void k_split_z(const float* __restrict__ z, int blk0) {
    const int tid  = threadIdx.x;
    const int blk  = blockIdx.x + blk0;
    const int b    = blk >> 2;
    const int toff = ((blk & 3) << 8) + tid;
    const int tok  = (b << 10) + toff;
    const float* zp = z + (size_t)b * D * HW + toff;
    uint4* Oh = reinterpret_cast<uint4*>(g_Ahi) + (size_t)tok * 32;
    uint4* Ol = reinterpret_cast<uint4*>(g_Alo) + (size_t)tok * 32;
    for (int g = 0; g < 32; g++) {
        uint32_t hv[4], lv[4];
        #pragma unroll
        for (int q = 0; q < 4; q++) {
            int d0 = (g * 4 + q) * 2;
            float v0 = zp[(size_t)d0 * HW];
            float v1 = zp[(size_t)(d0 + 1) * HW];
            hv[q] = packsplit(v0, v1, lv[q]);
        }
        Oh[g] = make_uint4(hv[0], hv[1], hv[2], hv[3]);
        Ol[g] = make_uint4(lv[0], lv[1], lv[2], lv[3]);
    }
}

// ---------------- split emb -> fp16 hi/lo + 0.5*||e||^2 ----------------
__global__ void k_split_emb(const float* __restrict__ emb) {
    const int wid  = threadIdx.x >> 5, lane = threadIdx.x & 31;
    const int code = blockIdx.x * 8 + wid;
    const float4* r = reinterpret_cast<const float4*>(emb + (size_t)code * D)
                    + lane * 2;
    float4 a = r[0], bq = r[1];
    float v[8] = {a.x, a.y, a.z, a.w, bq.x, bq.y, bq.z, bq.w};
    float s = 0.0f;
    uint32_t hv[4], lv[4];
    #pragma unroll
    for (int q = 0; q < 4; q++) {
        s += v[2*q] * v[2*q] + v[2*q+1] * v[2*q+1];
        hv[q] = packsplit(v[2*q], v[2*q+1], lv[q]);
    }
    reinterpret_cast<uint4*>(g_Bhi)[(size_t)code * 32 + lane] =
        make_uint4(hv[0], hv[1], hv[2], hv[3]);
    reinterpret_cast<uint4*>(g_Blo)[(size_t)code * 32 + lane] =
        make_uint4(lv[0], lv[1], lv[2], lv[3]);
    #pragma unroll
    for (int o = 16; o > 0; o >>= 1) s += __shfl_xor_sync(0xffffffffu, s, o);
    if (lane == 0) g_eh[code] = 0.5f * s;
}

// -------- main: 8-warp HMMA 3-product GEMM (f16-acc cross) + argmin + scatter
__global__ __launch_bounds__(256, 1)
void k_argmin(const float* __restrict__ emb,
              float* __restrict__ out_idx, float* __restrict__ out_zq) {
    extern __shared__ uint32_t sm[];
    const uint32_t sbase = smaddr(sm);
    float* Eh  = reinterpret_cast<float*>(sm + S_EH);
    int*   Ri  = reinterpret_cast<int*>(sm + S_RI);
    float* RED = reinterpret_cast<float*>(sm + S_RED);

    const int tid  = threadIdx.x;
    const int wid  = tid >> 5;
    const int lane = tid & 31;
    const int tok0 = blockIdx.x * TM;

    // ---- prologue: A (hi/lo, swizzled) + B chunk0 + Eh ----
    #pragma unroll 4
    for (int i = 0; i < 32; i++) {
        int grp = tid + 256 * i;
        int hl = grp >> 12, r = grp & 4095, row = r >> 5, g4 = (r & 31) << 2;
        const uint32_t* src = (hl ? g_Alo : g_Ahi)
                            + (size_t)(tok0 + row) * 128 + g4;
        uint32_t dst = sbase
            + ((hl ? S_ALO : S_AHI) + row * 128 + (g4 ^ ((row & 7) << 2))) * 4;
        cp16(dst, src);
    }
    #pragma unroll
    for (int i = 0; i < 8; i++) {
        int grp = tid + 256 * i;
        int hl = grp >> 10, r = grp & 1023, row = r >> 5, g4 = (r & 31) << 2;
        const uint32_t* src = (hl ? g_Blo : g_Bhi) + (size_t)row * 128 + g4;
        uint32_t dst = sbase
            + (S_B + hl * 4096 + row * 128 + (g4 ^ ((row & 7) << 2))) * 4;
        cp16(dst, src);
    }
    asm volatile("cp.async.commit_group;" ::: "memory");
    for (int i = tid; i < K; i += 256) Eh[i] = g_eh[i];
    asm volatile("cp.async.wait_group 0;" ::: "memory");
    __syncthreads();

    // ldmatrix lane geometry
    const int j  = lane >> 3;       // matrix index 0..3
    const int r8 = lane & 7;        // row within matrix
    const uint32_t ax  = (uint32_t)(r8 << 2);                 // swizzle term
    const uint32_t jjA = (uint32_t)((j >> 1) << 2);           // A k-half
    const uint32_t jbB = (uint32_t)((j & 1) << 2);            // B k-half
    const uint32_t aRow = (uint32_t)((wid * 16 + (j & 1) * 8 + r8) * 128);
    const uint32_t bRow0 = (uint32_t)(((j >> 1) * 8 + r8) * 128);        // tiles 0,1
    const uint32_t bRow1 = bRow0 + 16 * 128;                             // tiles 2,3

    float minv[2] = {CUDART_INF_F, CUDART_INF_F};
    int   mini[2] = {0, 0};

    for (int c = 0; c < NCHK; c++) {
        if (c + 1 < NCHK) {          // every warp copies its slice of chunk c+1
            const int code0 = (c + 1) * NB;
            const uint32_t bufo = (uint32_t)(S_B + ((c + 1) & 1) * 8192);
            #pragma unroll
            for (int i = 0; i < 8; i++) {
                int grp = tid + 256 * i;
                int hl = grp >> 10, rr = grp & 1023;
                int row = rr >> 5, g4 = (rr & 31) << 2;
                const uint32_t* src = (hl ? g_Blo : g_Bhi)
                                    + (size_t)(code0 + row) * 128 + g4;
                uint32_t dst = sbase + (bufo + hl * 4096
                               + row * 128 + (g4 ^ ((row & 7) << 2))) * 4;
                cp16(dst, src);
            }
            asm volatile("cp.async.commit_group;" ::: "memory");
        }

        // ---- compute chunk c ----
        const uint32_t bB = sbase + (uint32_t)(S_B + (c & 1) * 8192) * 4;
        const uint32_t aH = sbase + (uint32_t)S_AHI * 4;
        const uint32_t aL = sbase + (uint32_t)S_ALO * 4;
        float    accF[4][4];          // main product, f32 acc
        uint32_t accH[4][2];          // cross terms, f16 acc (2x half2)
        #pragma unroll
        for (int nt = 0; nt < 4; nt++) {
            #pragma unroll
            for (int e = 0; e < 4; e++) accF[nt][e] = 0.0f;
            accH[nt][0] = 0u; accH[nt][1] = 0u;
        }

        #pragma unroll 4
        for (int ks = 0; ks < 16; ks++) {
            const uint32_t tA = ((uint32_t)(ks * 8) + jjA) ^ ax;
            const uint32_t tB = ((uint32_t)(ks * 8) + jbB) ^ ax;
            uint32_t ah[4], al_[4], b01h[4], b23h[4], b01l[4], b23l[4];
            ldsm4(ah,   aH + (aRow + tA) * 4);
            ldsm4(al_,  aL + (aRow + tA) * 4);
            ldsm4(b01h, bB + (bRow0 + tB) * 4);
            ldsm4(b23h, bB + (bRow1 + tB) * 4);
            ldsm4(b01l, bB + 16384 + (bRow0 + tB) * 4);
            ldsm4(b23l, bB + 16384 + (bRow1 + tB) * 4);
            #pragma unroll
            for (int nt = 0; nt < 4; nt++) {
                const uint32_t* bh = (nt < 2) ? (b01h + 2 * nt) : (b23h + 2 * (nt - 2));
                const uint32_t* bl = (nt < 2) ? (b01l + 2 * nt) : (b23l + 2 * (nt - 2));
                mma_f16(accF[nt], ah, bh);          // f32 acc: main
                mma_f16h(accH[nt], ah,  bl);        // f16 acc: cross 1
                mma_f16h(accH[nt], al_, bh);        // f16 acc: cross 2
            }
        }

        // fold chunk into running argmin (ascending code order, strict <)
        const int cb = c * NB;
        #pragma unroll
        for (int nt = 0; nt < 4; nt++) {
            float2 x01 = __half22float2(*reinterpret_cast<__half2*>(&accH[nt][0]));
            float2 x23 = __half22float2(*reinterpret_cast<__half2*>(&accH[nt][1]));
            float xs[4] = {x01.x, x01.y, x23.x, x23.y};
            #pragma unroll
            for (int e = 0; e < 4; e++) {
                int code = cb + nt * 8 + 2 * (lane & 3) + (e & 1);
                float dist = Eh[code] - (accF[nt][e] + xs[e]);
                int s = e >> 1;
                if (dist < minv[s]) { minv[s] = dist; mini[s] = code; }
            }
        }

        if (c + 1 < NCHK)
            asm volatile("cp.async.wait_group 0;" ::: "memory");
        __syncthreads();
    }

    // ---- cross-lane argmin within quads (rows l>>2, l>>2+8) ----
    #pragma unroll
    for (int o = 1; o <= 2; o <<= 1)
        #pragma unroll
        for (int s = 0; s < 2; s++) {
            float ov = __shfl_xor_sync(0xffffffffu, minv[s], o);
            int   oi = __shfl_xor_sync(0xffffffffu, mini[s], o);
            if (ov < minv[s] || (ov == minv[s] && oi < mini[s])) {
                minv[s] = ov; mini[s] = oi;
            }
        }
    if ((lane & 3) == 0) {
        #pragma unroll
        for (int s = 0; s < 2; s++) {
            int row = wid * 16 + s * 8 + (lane >> 2);
            int bi  = mini[s];
            Ri[row] = bi;
            out_idx[tok0 + row] = (float)bi;
            atomicAdd(&g_counts[bi], 1.0f);
        }
    }
    __syncthreads();

    // ---- fused scatter: z reconstructed from smem hi+lo ----
    const int b    = tok0 >> 10;
    const int toff = tok0 & 1023;
    const int tk   = tid & 127;
    const int chh  = tid >> 7;
    const int kk   = Ri[tk];
    const int axr  = (tk & 7) << 2;
    const float* er  = emb + (size_t)kk * D;
    float*       dwr = g_dw + (size_t)kk * D;
    float*       qb  = out_zq + (size_t)b * D * HW + toff;
    const uint32_t* rowH = sm + S_AHI + tk * 128;
    const uint32_t* rowL = sm + S_ALO + tk * 128;

    float ls = 0.0f;
    for (int kp = chh * 64; kp < chh * 64 + 64; kp++) {
        uint32_t hv = rowH[kp ^ axr], lv = rowL[kp ^ axr];
        __half2 Hh = *reinterpret_cast<__half2*>(&hv);
        __half2 Ll = *reinterpret_cast<__half2*>(&lv);
        float z0 = __low2float(Hh)  + __low2float(Ll);
        float z1 = __high2float(Hh) + __high2float(Ll);
        int d0 = kp * 2;
        float2 ev = *reinterpret_cast<const float2*>(er + d0);
        float df0 = ev.x - z0, df1 = ev.y - z1;
        qb[(size_t)d0 * HW + tk]       = z0 + df0;
        qb[(size_t)(d0 + 1) * HW + tk] = z1 + df1;
        ls += df0 * df0 + df1 * df1;
        atomicAdd(dwr + d0,     z0);
        atomicAdd(dwr + d0 + 1, z1);
    }
    RED[tid] = ls;
    __syncthreads();
    #pragma unroll
    for (int s = 128; s > 0; s >>= 1) {
        if (tid < s) RED[tid] += RED[tid + s];
        __syncthreads();
    }
    if (tid == 0) atomicAdd(&g_loss, RED[0]);
}

// ---------------- tail kernels (consume + re-zero scratch) ----------------
__global__ void k_cs(const float* __restrict__ ecs, float* __restrict__ out_cs) {
    __shared__ float part[32];
    int k = threadIdx.x, lane = k & 31, w = k >> 5;
    float cr = 0.99f * ecs[k] + 0.01f * g_counts[k];
    g_counts[k] = 0.0f;
    float s = cr;
    #pragma unroll
    for (int o = 16; o > 0; o >>= 1) s += __shfl_xor_sync(0xffffffffu, s, o);
    if (lane == 0) part[w] = s;
    __syncthreads();
    if (w == 0) {
        float t = part[lane];
        #pragma unroll
        for (int o = 16; o > 0; o >>= 1) t += __shfl_xor_sync(0xffffffffu, t, o);
        if (lane == 0) part[0] = t;
    }
    __syncthreads();
    float n = part[0];
    out_cs[k] = (cr + 1e-5f) / (n + (float)K * 1e-5f) * n;
}

// NOTE: out_emaw/out_emb sit at odd float offsets in d_out -> scalar stores only.
__global__ void k_emb(const float* __restrict__ ema_w, const float* __restrict__ cs,
                      float* __restrict__ out_emaw, float* __restrict__ out_emb) {
    int i4 = (blockIdx.x * blockDim.x + threadIdx.x) * 4;
    if (i4 < K * D) {
        float4 w4 = *reinterpret_cast<const float4*>(ema_w + i4);
        float4 d4 = *reinterpret_cast<const float4*>(g_dw + i4);
        *reinterpret_cast<float4*>(g_dw + i4) = make_float4(0.f, 0.f, 0.f, 0.f);
        float inv = 1.0f / cs[i4 >> 8];
        float w0 = 0.99f * w4.x + 0.01f * d4.x;
        float w1 = 0.99f * w4.y + 0.01f * d4.y;
        float w2 = 0.99f * w4.z + 0.01f * d4.z;
        float w3 = 0.99f * w4.w + 0.01f * d4.w;
        out_emaw[i4 + 0] = w0;  out_emb[i4 + 0] = w0 * inv;
        out_emaw[i4 + 1] = w1;  out_emb[i4 + 1] = w1 * inv;
        out_emaw[i4 + 2] = w2;  out_emb[i4 + 2] = w2 * inv;
        out_emaw[i4 + 3] = w3;  out_emb[i4 + 3] = w3 * inv;
    }
}

__global__ void k_loss(float* __restrict__ out_loss) {
    if (threadIdx.x == 0) {
        out_loss[0] = 0.25f * g_loss / (float)((size_t)NTOK * D);
        g_loss = 0.0f;
    }
}

extern "C" void kernel_launch(void* const* d_in, const int* in_sizes, int n_in,
                              void* d_out, int out_size) {
    const float* z    = (const float*)d_in[0];
    const float* emb  = (const float*)d_in[1];
    const float* ecs  = (const float*)d_in[2];
    const float* emaw = (const float*)d_in[3];
    float* out = (float*)d_out;

    // output layout: z_q | idx | loss | new_embedding | cs | new_ema_w
    const size_t o_idx  = (size_t)NTOK * D;
    const size_t o_loss = o_idx + NTOK;
    const size_t o_emb  = o_loss + 1;
    const size_t o_cs   = o_emb + (size_t)K * D;
    const size_t o_emaw = o_cs + K;

    cudaFuncSetAttribute(k_argmin, cudaFuncAttributeMaxDynamicSharedMemorySize,
                         SMEM_BYTES);

    // k_argmin is deliberately the 4th launch: ncu's bounded capture has
    // profiled the 4th launch every round; this finally captures the hot kernel.
    k_split_emb <<<K / 8, 256>>>(emb);
    k_split_z   <<<64, 256>>>(z, 0);
    k_split_z   <<<64, 256>>>(z, 64);
    k_argmin    <<<NTOK / TM, 256, SMEM_BYTES>>>(emb, out + o_idx, out);
    k_cs        <<<1, K>>>(ecs, out + o_cs);
    k_emb       <<<K * D / 1024, 256>>>(emaw, out + o_cs,
                                        out + o_emaw, out + o_emb);
    k_loss      <<<1, 32>>>(out + o_loss);
}